// round 13
// baseline (speedup 1.0000x reference)
#include <cuda_runtime.h>
#include <cuda_bf16.h>
#include <cstdint>

// RecentAttention: N=500000, B=10000 sessions x L=50, H=128. Single persistent
// kernel, 2 CTAs/SM x 256 thr. Per CTA at init: compute a-rows for its own
// sessions (gather last rows + 64x128x128 bf16 MMA), keep 0.5a bf16 in smem.
// Per tile (2 sessions = 100 rows):
//   C = (0.5x)@W2^T + onehot(sess)@(0.5a)^T   (8+1 k16 steps, 32x64 warp tiles)
//   e = qb + sum 0.5q + sum 0.5q*tanh(C) ; per-session softmax ; pool (L2 x).
// x tile t+1 LDGs issued before pooling of tile t (latency hidden).

#define SA 136                  // smem row stride (bf16 elems), conflict-free
#define NTILE2 5000             // 2 sessions (100 rows) per tile

__device__ __forceinline__ void st4bf(__nv_bfloat16* p, float4 v) {
    *(__nv_bfloat162*)p       = __floats2bfloat162_rn(v.x, v.y);
    *(__nv_bfloat162*)(p + 2) = __floats2bfloat162_rn(v.z, v.w);
}

#define MMA16816(C, A, B0, B1)                                              \
    asm volatile("mma.sync.aligned.m16n8k16.row.col.f32.bf16.bf16.f32 "    \
        "{%0,%1,%2,%3}, {%4,%5,%6,%7}, {%8,%9}, {%0,%1,%2,%3};"            \
        : "+f"((C)[0]), "+f"((C)[1]), "+f"((C)[2]), "+f"((C)[3])           \
        : "r"((A)[0]), "r"((A)[1]), "r"((A)[2]), "r"((A)[3]),              \
          "r"(B0), "r"(B1))

#define LDSM4(R, a)                                                         \
    asm volatile("ldmatrix.sync.aligned.m8n8.x4.shared.b16 {%0,%1,%2,%3}, [%4];" \
        : "=r"((R)[0]), "=r"((R)[1]), "=r"((R)[2]), "=r"((R)[3]) : "r"(a))

// smem: Wsm@0(34816) Asm@34816(34816) Wext@69632(4096) qh@73728(512)
//       e_part@74240(1024) alpha@75264(512) ab_sm@75776(10240)  total 86016
#define K2_SMEM 86016

__global__ void __launch_bounds__(256, 2) k2_main(
    const float* __restrict__ x, const float* __restrict__ W1,
    const float* __restrict__ b1, const float* __restrict__ W2,
    const float* __restrict__ b2, const float* __restrict__ q,
    const float* __restrict__ qbp, const int* __restrict__ last_ixs,
    float* __restrict__ out)
{
    extern __shared__ char smraw[];
    __nv_bfloat16* Wsm  = (__nv_bfloat16*)smraw;
    __nv_bfloat16* Asm  = (__nv_bfloat16*)(smraw + 34816);
    __nv_bfloat16* Wext = (__nv_bfloat16*)(smraw + 69632);
    float* qh_sm  = (float*)(smraw + 73728);
    float* e_part = (float*)(smraw + 74240);    // [2][128]; init: bs + li
    float* alpha  = (float*)(smraw + 75264);    // [100]
    __nv_bfloat16* ab_sm = (__nv_bfloat16*)(smraw + 75776); // [<=40][128] 0.5a

    int tid = threadIdx.x, warp = tid >> 5, lane = tid & 31;
    int qq = lane >> 3, r7 = lane & 7;
    int grid = gridDim.x, bid = blockIdx.x;
    float qb = qbp[0];

    int nt = (NTILE2 - bid + grid - 1) / grid;  // tiles this CTA owns
    int rows2 = 2 * nt;                         // sessions (<= 40)
    int* lip = (int*)(e_part + 128);

    // ---------- init: W1, bs, li, gather, zero ----------
    if (tid < 128) {
        e_part[tid] = b1[tid] + b2[tid];        // bs
        qh_sm[tid] = 0.5f * q[tid];
    }
    if (tid < rows2) {
        int sess = 2 * (bid + (tid >> 1) * grid) + (tid & 1);
        lip[tid] = last_ixs[sess];
    }
    #pragma unroll
    for (int j = 0; j < 16; j++) {              // W1 -> bf16 smem
        int f4 = tid + j * 256, row = f4 >> 5, c4 = f4 & 31;
        st4bf(Wsm + row * SA + c4 * 4, ((const float4*)W1)[f4]);
    }
    #pragma unroll
    for (int j = 0; j < 34; j++)                // zero Asm (pad rows stay 0)
        ((uint32_t*)Asm)[tid + j * 256] = 0u;
    #pragma unroll
    for (int j = 0; j < 4; j++)                 // zero Wext (k>=2 stay 0)
        ((uint32_t*)Wext)[tid + j * 256] = 0u;
    __syncthreads();

    #pragma unroll
    for (int j = 0; j < 8; j++) {               // gather last rows -> Asm
        int f4 = tid + j * 256, row = f4 >> 5, c4 = f4 & 31;
        if (row < rows2)
            st4bf(Asm + row * SA + c4 * 4,
                  ((const float4*)(x + (size_t)lip[row] * 128))[c4]);
    }
    __syncthreads();

    uint32_t asm_u  = (uint32_t)__cvta_generic_to_shared(Asm);
    uint32_t wsm_u  = (uint32_t)__cvta_generic_to_shared(Wsm);
    uint32_t wext_u = (uint32_t)__cvta_generic_to_shared(Wext);

    // ---------- init MMA: a = x_last @ W1^T + bs ; ab_sm = bf16(0.5a) ------
    {
        int m0i = (warp & 1) * 32, n0i = (warp >> 1) * 32;
        uint32_t ab = asm_u + 2 * ((m0i + (qq & 1) * 8 + r7) * SA + (qq >> 1) * 8);
        uint32_t bb = wsm_u + 2 * ((n0i + (qq >> 1) * 8 + r7) * SA + (qq & 1) * 8);
        float c[2][4][4] = {};
        #pragma unroll
        for (int ks = 0; ks < 8; ks++) {
            uint32_t A0[4], A1[4], B0[4], B1[4];
            LDSM4(A0, ab + ks * 32);
            LDSM4(A1, ab + 16 * SA * 2 + ks * 32);
            LDSM4(B0, bb + ks * 32);
            LDSM4(B1, bb + 16 * SA * 2 + ks * 32);
            MMA16816(c[0][0], A0, B0[0], B0[1]);
            MMA16816(c[0][1], A0, B0[2], B0[3]);
            MMA16816(c[0][2], A0, B1[0], B1[1]);
            MMA16816(c[0][3], A0, B1[2], B1[3]);
            MMA16816(c[1][0], A1, B0[0], B0[1]);
            MMA16816(c[1][1], A1, B0[2], B0[3]);
            MMA16816(c[1][2], A1, B1[0], B1[1]);
            MMA16816(c[1][3], A1, B1[2], B1[3]);
        }
        #pragma unroll
        for (int mi = 0; mi < 2; mi++)
            #pragma unroll
            for (int ni = 0; ni < 4; ni++) {
                int col = n0i + ni * 8 + (lane & 3) * 2;
                #pragma unroll
                for (int r2 = 0; r2 < 2; r2++) {
                    int row = m0i + mi * 16 + (lane >> 2) + 8 * r2;
                    if (row < rows2) {
                        float a0 = 0.5f * (c[mi][ni][2 * r2]     + e_part[col]);
                        float a1 = 0.5f * (c[mi][ni][2 * r2 + 1] + e_part[col + 1]);
                        *(__nv_bfloat162*)(ab_sm + row * 128 + col) =
                            __floats2bfloat162_rn(a0, a1);
                    }
                }
            }
    }
    __syncthreads();                            // Wsm/Asm free; ab_sm done

    #pragma unroll
    for (int j = 0; j < 16; j++) {              // W2 -> bf16 smem (overwrite)
        int f4 = tid + j * 256, row = f4 >> 5, c4 = f4 & 31;
        st4bf(Wsm + row * SA + c4 * 4, ((const float4*)W2)[f4]);
    }

    // ---------- main loop setup ----------
    int m0 = (warp & 3) * 32;                   // warp tile: 32 rows x 64 cols
    int n0 = (warp >> 2) * 64;
    uint32_t abase = asm_u + 2 * ((m0 + (qq & 1) * 8 + r7) * SA + (qq >> 1) * 8);
    uint32_t bbase = wsm_u + 2 * ((n0 + (qq >> 1) * 8 + r7) * SA + (qq & 1) * 8);
    uint32_t ebase = wext_u + (n0 + (qq >> 1) * 8 + r7) * 32 + (qq & 1) * 16;

    // one-hot session-indicator A fragments (k=0 -> sess0, k=1 -> sess1)
    int klo = (lane & 3) * 2;
    uint32_t Aext[2][4];
    #pragma unroll
    for (int mi = 0; mi < 2; mi++) {
        #pragma unroll
        for (int h = 0; h < 2; h++) {
            int row = m0 + mi * 16 + (lane >> 2) + 8 * h;
            int sess = (row < 50) ? 0 : (row < 100) ? 1 : -1;
            uint32_t v = 0;
            if (sess == klo)     v |= 0x3F80u;
            if (sess == klo + 1) v |= 0x3F800000u;
            Aext[mi][h] = v;
        }
        Aext[mi][2] = 0u; Aext[mi][3] = 0u;
    }

    float csum = 0.f;                           // sum of 0.5*q over warp's cols
    #pragma unroll
    for (int g = 0; g < 16; g++) {
        float4 qv = *(const float4*)(qh_sm + n0 + g * 4);
        csum += qv.x + qv.y + qv.z + qv.w;
    }

    // prologue: LDG batch for first tile
    float4 v[13];
    {
        const float* xt = x + (size_t)bid * 12800;
        #pragma unroll
        for (int j = 0; j < 13; j++) {
            int f4 = tid + j * 256;
            if (f4 < 3200) v[j] = ((const float4*)xt)[f4];
        }
    }

    int it = 0;
    for (int t = bid; t < NTILE2; t += grid, it++) {
        // ---- fill: 0.5*v -> bf16 Asm ; Wext from ab_sm ----
        #pragma unroll
        for (int j = 0; j < 13; j++) {
            int f4 = tid + j * 256;
            if (f4 < 3200) {
                float4 w = v[j];
                w.x *= 0.5f; w.y *= 0.5f; w.z *= 0.5f; w.w *= 0.5f;
                st4bf(Asm + (f4 >> 5) * SA + (f4 & 31) * 4, w);
            }
        }
        {
            int k = tid >> 7, col = tid & 127;
            Wext[col * 16 + k] = ab_sm[(2 * it + k) * 128 + col];
        }
        __syncthreads();                        // MMA operands ready

        // ---- MMA: C = (0.5x)@W2^T + onehot@(0.5a)^T  (32x64 single pass) ----
        float c[2][8][4] = {};
        #pragma unroll
        for (int ks = 0; ks < 8; ks++) {
            uint32_t A0[4], A1[4], B0[4], B1[4], B2[4], B3[4];
            LDSM4(A0, abase + ks * 32);
            LDSM4(A1, abase + 16 * SA * 2 + ks * 32);
            LDSM4(B0, bbase + ks * 32);
            LDSM4(B1, bbase + 16 * SA * 2 + ks * 32);
            LDSM4(B2, bbase + 32 * SA * 2 + ks * 32);
            LDSM4(B3, bbase + 48 * SA * 2 + ks * 32);
            MMA16816(c[0][0], A0, B0[0], B0[1]); MMA16816(c[1][0], A1, B0[0], B0[1]);
            MMA16816(c[0][1], A0, B0[2], B0[3]); MMA16816(c[1][1], A1, B0[2], B0[3]);
            MMA16816(c[0][2], A0, B1[0], B1[1]); MMA16816(c[1][2], A1, B1[0], B1[1]);
            MMA16816(c[0][3], A0, B1[2], B1[3]); MMA16816(c[1][3], A1, B1[2], B1[3]);
            MMA16816(c[0][4], A0, B2[0], B2[1]); MMA16816(c[1][4], A1, B2[0], B2[1]);
            MMA16816(c[0][5], A0, B2[2], B2[3]); MMA16816(c[1][5], A1, B2[2], B2[3]);
            MMA16816(c[0][6], A0, B3[0], B3[1]); MMA16816(c[1][6], A1, B3[0], B3[1]);
            MMA16816(c[0][7], A0, B3[2], B3[3]); MMA16816(c[1][7], A1, B3[2], B3[3]);
        }
        {   // 9th k-step: per-session bias
            uint32_t B0[4], B1[4], B2[4], B3[4];
            LDSM4(B0, ebase);
            LDSM4(B1, ebase + 16 * 32);
            LDSM4(B2, ebase + 32 * 32);
            LDSM4(B3, ebase + 48 * 32);
            MMA16816(c[0][0], Aext[0], B0[0], B0[1]); MMA16816(c[1][0], Aext[1], B0[0], B0[1]);
            MMA16816(c[0][1], Aext[0], B0[2], B0[3]); MMA16816(c[1][1], Aext[1], B0[2], B0[3]);
            MMA16816(c[0][2], Aext[0], B1[0], B1[1]); MMA16816(c[1][2], Aext[1], B1[0], B1[1]);
            MMA16816(c[0][3], Aext[0], B1[2], B1[3]); MMA16816(c[1][3], Aext[1], B1[2], B1[3]);
            MMA16816(c[0][4], Aext[0], B2[0], B2[1]); MMA16816(c[1][4], Aext[1], B2[0], B2[1]);
            MMA16816(c[0][5], Aext[0], B2[2], B2[3]); MMA16816(c[1][5], Aext[1], B2[2], B2[3]);
            MMA16816(c[0][6], Aext[0], B3[0], B3[1]); MMA16816(c[1][6], Aext[1], B3[0], B3[1]);
            MMA16816(c[0][7], Aext[0], B3[2], B3[3]); MMA16816(c[1][7], Aext[1], B3[2], B3[3]);
        }

        // ---- epilogue: e partials = csum + sum 0.5*q*tanh(C) ----
        float pe[2][2] = {};
        #pragma unroll
        for (int ni = 0; ni < 8; ni++) {
            int col = n0 + ni * 8 + (lane & 3) * 2;
            float q0 = qh_sm[col], q1 = qh_sm[col + 1];
            #pragma unroll
            for (int mi = 0; mi < 2; mi++)
                #pragma unroll
                for (int r2 = 0; r2 < 2; r2++) {
                    int row = m0 + mi * 16 + (lane >> 2) + 8 * r2;
                    if (row < 100) {
                        float t0, t1;
                        asm("tanh.approx.f32 %0, %1;" : "=f"(t0) : "f"(c[mi][ni][2 * r2]));
                        asm("tanh.approx.f32 %0, %1;" : "=f"(t1) : "f"(c[mi][ni][2 * r2 + 1]));
                        pe[mi][r2] = fmaf(q0, t0, fmaf(q1, t1, pe[mi][r2]));
                    }
                }
        }
        #pragma unroll
        for (int mi = 0; mi < 2; mi++)
            #pragma unroll
            for (int r2 = 0; r2 < 2; r2++) {
                float vv = pe[mi][r2];
                vv += __shfl_xor_sync(0xffffffffu, vv, 1);
                vv += __shfl_xor_sync(0xffffffffu, vv, 2);
                if ((lane & 3) == 0) {
                    int row = m0 + mi * 16 + (lane >> 2) + 8 * r2;
                    e_part[(warp >> 2) * 128 + row] = vv + csum;
                }
            }
        __syncthreads();

        // ---- per-session softmax over 50 rows (warps 0,1) ----
        if (warp < 2) {
            int rb = warp * 50;
            int i1 = rb + lane;
            bool v2 = lane < 18;
            int i2 = rb + 32 + lane;
            float e1 = e_part[i1] + e_part[128 + i1] + qb;
            float e2 = v2 ? (e_part[i2] + e_part[128 + i2] + qb) : -1e30f;
            float m = fmaxf(e1, e2);
            #pragma unroll
            for (int o = 16; o; o >>= 1) m = fmaxf(m, __shfl_xor_sync(0xffffffffu, m, o));
            float z1 = __expf(e1 - m);
            float z2 = v2 ? __expf(e2 - m) : 0.f;
            float s = z1 + z2;
            #pragma unroll
            for (int o = 16; o; o >>= 1) s += __shfl_xor_sync(0xffffffffu, s, o);
            float inv = __frcp_rn(s);
            alpha[i1] = z1 * inv;
            if (v2) alpha[i2] = z2 * inv;
        }
        __syncthreads();

        // ---- issue next tile's LDGs (latency hidden under pooling) ----
        int tn = t + grid;
        if (tn < NTILE2) {
            const float* xt2 = x + (size_t)tn * 12800;
            #pragma unroll
            for (int j = 0; j < 13; j++) {
                int f4 = tid + j * 256;
                if (f4 < 3200) v[j] = ((const float4*)xt2)[f4];
            }
        }

        // ---- pooling: out[2t+s][col] = sum_j alpha_j * x_j[col] (fp32, L2) ----
        {
            int s = tid >> 7, col = tid & 127;
            const float* xr = x + (size_t)t * 12800 + s * 6400 + col;
            const float* al = alpha + s * 50;
            float acc = 0.f;
            #pragma unroll 10
            for (int j = 0; j < 50; j++) acc = fmaf(al[j], xr[j * 128], acc);
            out[(size_t)(2 * t + s) * 128 + col] = acc;
        }
        __syncthreads();                        // alpha/Asm safe to overwrite
    }
}

extern "C" void kernel_launch(void* const* d_in, const int* in_sizes, int n_in,
                              void* d_out, int out_size)
{
    const float* x   = (const float*)d_in[0];
    const float* W1w = (const float*)d_in[1];
    const float* W1b = (const float*)d_in[2];
    const float* W2w = (const float*)d_in[3];
    const float* W2b = (const float*)d_in[4];
    const float* qw  = (const float*)d_in[5];
    const float* qb  = (const float*)d_in[6];
    const int* last  = (const int*)d_in[8];
    float* out = (float*)d_out;

    cudaFuncSetAttribute(k2_main, cudaFuncAttributeMaxDynamicSharedMemorySize,
                         K2_SMEM);

    int nsm = 148;
    cudaDeviceGetAttribute(&nsm, cudaDevAttrMultiProcessorCount, 0);

    k2_main<<<2 * nsm, 256, K2_SMEM>>>(x, W1w, W1b, W2w, W2b, qw, qb, last, out);
}

// round 14
// speedup vs baseline: 1.3064x; 1.3064x over previous
#include <cuda_runtime.h>
#include <cuda_bf16.h>
#include <cstdint>

// RecentAttention: N=500000, B=10000 sessions x L=50, H=128. Single persistent
// kernel, 2 CTAs/SM x 256 thr. Per CTA at init: compute a-rows for its own
// sessions (gather last rows + 64x128x128 bf16 MMA), keep 0.5a bf16 in smem.
// Per tile (2 sessions = 100 rows):
//   C = (0.5x)@W2^T + onehot(sess)@(0.5a)^T   (8+1 k16 steps, 32x64 warp tiles)
//   e = qb + sum 0.5q + sum 0.5q*tanh(C) ; per-session softmax ; pool (L2 x).
// R14: LDG batch for tile t at loop top (R12 schedule) -- v[] dead during MMA,
// no spill (R13 regression root cause).

#define SA 136                  // smem row stride (bf16 elems), conflict-free
#define NTILE2 5000             // 2 sessions (100 rows) per tile

__device__ __forceinline__ void st4bf(__nv_bfloat16* p, float4 v) {
    *(__nv_bfloat162*)p       = __floats2bfloat162_rn(v.x, v.y);
    *(__nv_bfloat162*)(p + 2) = __floats2bfloat162_rn(v.z, v.w);
}

#define MMA16816(C, A, B0, B1)                                              \
    asm volatile("mma.sync.aligned.m16n8k16.row.col.f32.bf16.bf16.f32 "    \
        "{%0,%1,%2,%3}, {%4,%5,%6,%7}, {%8,%9}, {%0,%1,%2,%3};"            \
        : "+f"((C)[0]), "+f"((C)[1]), "+f"((C)[2]), "+f"((C)[3])           \
        : "r"((A)[0]), "r"((A)[1]), "r"((A)[2]), "r"((A)[3]),              \
          "r"(B0), "r"(B1))

#define LDSM4(R, a)                                                         \
    asm volatile("ldmatrix.sync.aligned.m8n8.x4.shared.b16 {%0,%1,%2,%3}, [%4];" \
        : "=r"((R)[0]), "=r"((R)[1]), "=r"((R)[2]), "=r"((R)[3]) : "r"(a))

// smem: Wsm@0(34816) Asm@34816(34816) Wext@69632(4096) qh@73728(512)
//       e_part@74240(1024) alpha@75264(512) ab_sm@75776(10240)  total 86016
#define K2_SMEM 86016

__global__ void __launch_bounds__(256, 2) k2_main(
    const float* __restrict__ x, const float* __restrict__ W1,
    const float* __restrict__ b1, const float* __restrict__ W2,
    const float* __restrict__ b2, const float* __restrict__ q,
    const float* __restrict__ qbp, const int* __restrict__ last_ixs,
    float* __restrict__ out)
{
    extern __shared__ char smraw[];
    __nv_bfloat16* Wsm  = (__nv_bfloat16*)smraw;
    __nv_bfloat16* Asm  = (__nv_bfloat16*)(smraw + 34816);
    __nv_bfloat16* Wext = (__nv_bfloat16*)(smraw + 69632);
    float* qh_sm  = (float*)(smraw + 73728);
    float* e_part = (float*)(smraw + 74240);    // [2][128]; init: bs + li
    float* alpha  = (float*)(smraw + 75264);    // [100]
    __nv_bfloat16* ab_sm = (__nv_bfloat16*)(smraw + 75776); // [<=40][128] 0.5a

    int tid = threadIdx.x, warp = tid >> 5, lane = tid & 31;
    int qq = lane >> 3, r7 = lane & 7;
    int grid = gridDim.x, bid = blockIdx.x;
    float qb = qbp[0];

    int nt = (NTILE2 - bid + grid - 1) / grid;  // tiles this CTA owns
    int rows2 = 2 * nt;                         // sessions (<= 40)
    int* lip = (int*)(e_part + 128);

    // ---------- init: W1, bs, li, gather, zero ----------
    if (tid < 128) {
        e_part[tid] = b1[tid] + b2[tid];        // bs
        qh_sm[tid] = 0.5f * q[tid];
    }
    if (tid < rows2) {
        int sess = 2 * (bid + (tid >> 1) * grid) + (tid & 1);
        lip[tid] = last_ixs[sess];
    }
    #pragma unroll
    for (int j = 0; j < 16; j++) {              // W1 -> bf16 smem
        int f4 = tid + j * 256, row = f4 >> 5, c4 = f4 & 31;
        st4bf(Wsm + row * SA + c4 * 4, ((const float4*)W1)[f4]);
    }
    #pragma unroll
    for (int j = 0; j < 34; j++)                // zero Asm (pad rows stay 0)
        ((uint32_t*)Asm)[tid + j * 256] = 0u;
    #pragma unroll
    for (int j = 0; j < 4; j++)                 // zero Wext (k>=2 stay 0)
        ((uint32_t*)Wext)[tid + j * 256] = 0u;
    __syncthreads();

    #pragma unroll
    for (int j = 0; j < 8; j++) {               // gather last rows -> Asm
        int f4 = tid + j * 256, row = f4 >> 5, c4 = f4 & 31;
        if (row < rows2)
            st4bf(Asm + row * SA + c4 * 4,
                  ((const float4*)(x + (size_t)lip[row] * 128))[c4]);
    }
    __syncthreads();

    uint32_t asm_u  = (uint32_t)__cvta_generic_to_shared(Asm);
    uint32_t wsm_u  = (uint32_t)__cvta_generic_to_shared(Wsm);
    uint32_t wext_u = (uint32_t)__cvta_generic_to_shared(Wext);

    // ---------- init MMA: a = x_last @ W1^T + bs ; ab_sm = bf16(0.5a) ------
    {
        int m0i = (warp & 1) * 32, n0i = (warp >> 1) * 32;
        uint32_t ab = asm_u + 2 * ((m0i + (qq & 1) * 8 + r7) * SA + (qq >> 1) * 8);
        uint32_t bb = wsm_u + 2 * ((n0i + (qq >> 1) * 8 + r7) * SA + (qq & 1) * 8);
        float c[2][4][4] = {};
        #pragma unroll
        for (int ks = 0; ks < 8; ks++) {
            uint32_t A0[4], A1[4], B0[4], B1[4];
            LDSM4(A0, ab + ks * 32);
            LDSM4(A1, ab + 16 * SA * 2 + ks * 32);
            LDSM4(B0, bb + ks * 32);
            LDSM4(B1, bb + 16 * SA * 2 + ks * 32);
            MMA16816(c[0][0], A0, B0[0], B0[1]);
            MMA16816(c[0][1], A0, B0[2], B0[3]);
            MMA16816(c[0][2], A0, B1[0], B1[1]);
            MMA16816(c[0][3], A0, B1[2], B1[3]);
            MMA16816(c[1][0], A1, B0[0], B0[1]);
            MMA16816(c[1][1], A1, B0[2], B0[3]);
            MMA16816(c[1][2], A1, B1[0], B1[1]);
            MMA16816(c[1][3], A1, B1[2], B1[3]);
        }
        #pragma unroll
        for (int mi = 0; mi < 2; mi++)
            #pragma unroll
            for (int ni = 0; ni < 4; ni++) {
                int col = n0i + ni * 8 + (lane & 3) * 2;
                #pragma unroll
                for (int r2 = 0; r2 < 2; r2++) {
                    int row = m0i + mi * 16 + (lane >> 2) + 8 * r2;
                    if (row < rows2) {
                        float a0 = 0.5f * (c[mi][ni][2 * r2]     + e_part[col]);
                        float a1 = 0.5f * (c[mi][ni][2 * r2 + 1] + e_part[col + 1]);
                        *(__nv_bfloat162*)(ab_sm + row * 128 + col) =
                            __floats2bfloat162_rn(a0, a1);
                    }
                }
            }
    }
    __syncthreads();                            // Wsm/Asm free; ab_sm done

    #pragma unroll
    for (int j = 0; j < 16; j++) {              // W2 -> bf16 smem (overwrite)
        int f4 = tid + j * 256, row = f4 >> 5, c4 = f4 & 31;
        st4bf(Wsm + row * SA + c4 * 4, ((const float4*)W2)[f4]);
    }

    // ---------- main loop setup ----------
    int m0 = (warp & 3) * 32;                   // warp tile: 32 rows x 64 cols
    int n0 = (warp >> 2) * 64;
    uint32_t abase = asm_u + 2 * ((m0 + (qq & 1) * 8 + r7) * SA + (qq >> 1) * 8);
    uint32_t bbase = wsm_u + 2 * ((n0 + (qq >> 1) * 8 + r7) * SA + (qq & 1) * 8);
    uint32_t ebase = wext_u + (n0 + (qq >> 1) * 8 + r7) * 32 + (qq & 1) * 16;

    // one-hot session-indicator A fragments (k=0 -> sess0, k=1 -> sess1)
    int klo = (lane & 3) * 2;
    uint32_t Aext[2][4];
    #pragma unroll
    for (int mi = 0; mi < 2; mi++) {
        #pragma unroll
        for (int h = 0; h < 2; h++) {
            int row = m0 + mi * 16 + (lane >> 2) + 8 * h;
            int sess = (row < 50) ? 0 : (row < 100) ? 1 : -1;
            uint32_t v = 0;
            if (sess == klo)     v |= 0x3F80u;
            if (sess == klo + 1) v |= 0x3F800000u;
            Aext[mi][h] = v;
        }
        Aext[mi][2] = 0u; Aext[mi][3] = 0u;
    }

    float csum = 0.f;                           // sum of 0.5*q over warp's cols
    #pragma unroll
    for (int g = 0; g < 16; g++) {
        float4 qv = *(const float4*)(qh_sm + n0 + g * 4);
        csum += qv.x + qv.y + qv.z + qv.w;
    }

    int it = 0;
    for (int t = bid; t < NTILE2; t += grid, it++) {
        const float* xt = x + (size_t)t * 12800;

        // ---- fill: x tile LDG batch -> 0.5x bf16 Asm ; Wext from ab_sm ----
        float4 v[13];
        #pragma unroll
        for (int j = 0; j < 13; j++) {
            int f4 = tid + j * 256;
            if (f4 < 3200) v[j] = ((const float4*)xt)[f4];
        }
        #pragma unroll
        for (int j = 0; j < 13; j++) {
            int f4 = tid + j * 256;
            if (f4 < 3200) {
                float4 w = v[j];
                w.x *= 0.5f; w.y *= 0.5f; w.z *= 0.5f; w.w *= 0.5f;
                st4bf(Asm + (f4 >> 5) * SA + (f4 & 31) * 4, w);
            }
        }
        {
            int k = tid >> 7, col = tid & 127;
            Wext[col * 16 + k] = ab_sm[(2 * it + k) * 128 + col];
        }
        __syncthreads();                        // MMA operands ready

        // ---- MMA: C = (0.5x)@W2^T + onehot@(0.5a)^T  (32x64 single pass) ----
        float c[2][8][4] = {};
        #pragma unroll
        for (int ks = 0; ks < 8; ks++) {
            uint32_t A0[4], A1[4], B0[4], B1[4], B2[4], B3[4];
            LDSM4(A0, abase + ks * 32);
            LDSM4(A1, abase + 16 * SA * 2 + ks * 32);
            LDSM4(B0, bbase + ks * 32);
            LDSM4(B1, bbase + 16 * SA * 2 + ks * 32);
            LDSM4(B2, bbase + 32 * SA * 2 + ks * 32);
            LDSM4(B3, bbase + 48 * SA * 2 + ks * 32);
            MMA16816(c[0][0], A0, B0[0], B0[1]); MMA16816(c[1][0], A1, B0[0], B0[1]);
            MMA16816(c[0][1], A0, B0[2], B0[3]); MMA16816(c[1][1], A1, B0[2], B0[3]);
            MMA16816(c[0][2], A0, B1[0], B1[1]); MMA16816(c[1][2], A1, B1[0], B1[1]);
            MMA16816(c[0][3], A0, B1[2], B1[3]); MMA16816(c[1][3], A1, B1[2], B1[3]);
            MMA16816(c[0][4], A0, B2[0], B2[1]); MMA16816(c[1][4], A1, B2[0], B2[1]);
            MMA16816(c[0][5], A0, B2[2], B2[3]); MMA16816(c[1][5], A1, B2[2], B2[3]);
            MMA16816(c[0][6], A0, B3[0], B3[1]); MMA16816(c[1][6], A1, B3[0], B3[1]);
            MMA16816(c[0][7], A0, B3[2], B3[3]); MMA16816(c[1][7], A1, B3[2], B3[3]);
        }
        {   // 9th k-step: per-session bias
            uint32_t B0[4], B1[4], B2[4], B3[4];
            LDSM4(B0, ebase);
            LDSM4(B1, ebase + 16 * 32);
            LDSM4(B2, ebase + 32 * 32);
            LDSM4(B3, ebase + 48 * 32);
            MMA16816(c[0][0], Aext[0], B0[0], B0[1]); MMA16816(c[1][0], Aext[1], B0[0], B0[1]);
            MMA16816(c[0][1], Aext[0], B0[2], B0[3]); MMA16816(c[1][1], Aext[1], B0[2], B0[3]);
            MMA16816(c[0][2], Aext[0], B1[0], B1[1]); MMA16816(c[1][2], Aext[1], B1[0], B1[1]);
            MMA16816(c[0][3], Aext[0], B1[2], B1[3]); MMA16816(c[1][3], Aext[1], B1[2], B1[3]);
            MMA16816(c[0][4], Aext[0], B2[0], B2[1]); MMA16816(c[1][4], Aext[1], B2[0], B2[1]);
            MMA16816(c[0][5], Aext[0], B2[2], B2[3]); MMA16816(c[1][5], Aext[1], B2[2], B2[3]);
            MMA16816(c[0][6], Aext[0], B3[0], B3[1]); MMA16816(c[1][6], Aext[1], B3[0], B3[1]);
            MMA16816(c[0][7], Aext[0], B3[2], B3[3]); MMA16816(c[1][7], Aext[1], B3[2], B3[3]);
        }

        // ---- epilogue: e partials = csum + sum 0.5*q*tanh(C) ----
        float pe[2][2] = {};
        #pragma unroll
        for (int ni = 0; ni < 8; ni++) {
            int col = n0 + ni * 8 + (lane & 3) * 2;
            float q0 = qh_sm[col], q1 = qh_sm[col + 1];
            #pragma unroll
            for (int mi = 0; mi < 2; mi++)
                #pragma unroll
                for (int r2 = 0; r2 < 2; r2++) {
                    int row = m0 + mi * 16 + (lane >> 2) + 8 * r2;
                    if (row < 100) {
                        float t0, t1;
                        asm("tanh.approx.f32 %0, %1;" : "=f"(t0) : "f"(c[mi][ni][2 * r2]));
                        asm("tanh.approx.f32 %0, %1;" : "=f"(t1) : "f"(c[mi][ni][2 * r2 + 1]));
                        pe[mi][r2] = fmaf(q0, t0, fmaf(q1, t1, pe[mi][r2]));
                    }
                }
        }
        #pragma unroll
        for (int mi = 0; mi < 2; mi++)
            #pragma unroll
            for (int r2 = 0; r2 < 2; r2++) {
                float vv = pe[mi][r2];
                vv += __shfl_xor_sync(0xffffffffu, vv, 1);
                vv += __shfl_xor_sync(0xffffffffu, vv, 2);
                if ((lane & 3) == 0) {
                    int row = m0 + mi * 16 + (lane >> 2) + 8 * r2;
                    e_part[(warp >> 2) * 128 + row] = vv + csum;
                }
            }
        __syncthreads();

        // ---- per-session softmax over 50 rows (warps 0,1) ----
        if (warp < 2) {
            int rb = warp * 50;
            int i1 = rb + lane;
            bool v2 = lane < 18;
            int i2 = rb + 32 + lane;
            float e1 = e_part[i1] + e_part[128 + i1] + qb;
            float e2 = v2 ? (e_part[i2] + e_part[128 + i2] + qb) : -1e30f;
            float m = fmaxf(e1, e2);
            #pragma unroll
            for (int o = 16; o; o >>= 1) m = fmaxf(m, __shfl_xor_sync(0xffffffffu, m, o));
            float z1 = __expf(e1 - m);
            float z2 = v2 ? __expf(e2 - m) : 0.f;
            float s = z1 + z2;
            #pragma unroll
            for (int o = 16; o; o >>= 1) s += __shfl_xor_sync(0xffffffffu, s, o);
            float inv = __frcp_rn(s);
            alpha[i1] = z1 * inv;
            if (v2) alpha[i2] = z2 * inv;
        }
        __syncthreads();

        // ---- pooling: out[2t+s][col] = sum_j alpha_j * x_j[col] (fp32, L2) ----
        {
            int s = tid >> 7, col = tid & 127;
            const float* xr = xt + s * 6400 + col;
            const float* al = alpha + s * 50;
            float acc = 0.f;
            #pragma unroll 10
            for (int j = 0; j < 50; j++) acc = fmaf(al[j], xr[j * 128], acc);
            out[(size_t)(2 * t + s) * 128 + col] = acc;
        }
        __syncthreads();                        // alpha/Asm safe to overwrite
    }
}

extern "C" void kernel_launch(void* const* d_in, const int* in_sizes, int n_in,
                              void* d_out, int out_size)
{
    const float* x   = (const float*)d_in[0];
    const float* W1w = (const float*)d_in[1];
    const float* W1b = (const float*)d_in[2];
    const float* W2w = (const float*)d_in[3];
    const float* W2b = (const float*)d_in[4];
    const float* qw  = (const float*)d_in[5];
    const float* qb  = (const float*)d_in[6];
    const int* last  = (const int*)d_in[8];
    float* out = (float*)d_out;

    cudaFuncSetAttribute(k2_main, cudaFuncAttributeMaxDynamicSharedMemorySize,
                         K2_SMEM);

    int nsm = 148;
    cudaDeviceGetAttribute(&nsm, cudaDevAttrMultiProcessorCount, 0);

    k2_main<<<2 * nsm, 256, K2_SMEM>>>(x, W1w, W1b, W2w, W2b, qw, qb, last, out);
}

// round 15
// speedup vs baseline: 1.5076x; 1.1540x over previous
#include <cuda_runtime.h>
#include <cuda_bf16.h>
#include <cstdint>

// RecentAttention: N=500000, B=10000 sessions x L=50, H=128. Single persistent
// kernel, 2 CTAs/SM x 256 thr. Init: per-CTA a-rows (gather + 64x128x128 MMA),
// 0.5a bf16 in smem. Per tile (2 sessions = 100 rows):
//   MMA: C = (0.5x)@W2^T + onehot(sess)@(0.5a)^T  (8+1 k16, 32x64 warp tiles)
//   epilogue e = csum + sum 0.5q*tanh(C) -> sync ->
//   {warps0-1: softmax(t) || warps2-7: fill Asm(t+1) + Wext(t+1)} -> sync ->
//   pooling(t) from L2 x.  (2 syncs/tile; fill latency hidden under softmax)

#define SA 136                  // smem row stride (bf16 elems), conflict-free
#define NTILE2 5000             // 2 sessions (100 rows) per tile

__device__ __forceinline__ void st4bf(__nv_bfloat16* p, float4 v) {
    *(__nv_bfloat162*)p       = __floats2bfloat162_rn(v.x, v.y);
    *(__nv_bfloat162*)(p + 2) = __floats2bfloat162_rn(v.z, v.w);
}

#define MMA16816(C, A, B0, B1)                                              \
    asm volatile("mma.sync.aligned.m16n8k16.row.col.f32.bf16.bf16.f32 "    \
        "{%0,%1,%2,%3}, {%4,%5,%6,%7}, {%8,%9}, {%0,%1,%2,%3};"            \
        : "+f"((C)[0]), "+f"((C)[1]), "+f"((C)[2]), "+f"((C)[3])           \
        : "r"((A)[0]), "r"((A)[1]), "r"((A)[2]), "r"((A)[3]),              \
          "r"(B0), "r"(B1))

#define LDSM4(R, a)                                                         \
    asm volatile("ldmatrix.sync.aligned.m8n8.x4.shared.b16 {%0,%1,%2,%3}, [%4];" \
        : "=r"((R)[0]), "=r"((R)[1]), "=r"((R)[2]), "=r"((R)[3]) : "r"(a))

// smem: Wsm@0(34816) Asm@34816(34816) Wext@69632(4096) qh@73728(512)
//       e_part@74240(1024) alpha@75264(512: 2x52 padded) ab_sm@75776(10240)
#define K2_SMEM 86016

__global__ void __launch_bounds__(256, 2) k2_main(
    const float* __restrict__ x, const float* __restrict__ W1,
    const float* __restrict__ b1, const float* __restrict__ W2,
    const float* __restrict__ b2, const float* __restrict__ q,
    const float* __restrict__ qbp, const int* __restrict__ last_ixs,
    float* __restrict__ out)
{
    extern __shared__ char smraw[];
    __nv_bfloat16* Wsm  = (__nv_bfloat16*)smraw;
    __nv_bfloat16* Asm  = (__nv_bfloat16*)(smraw + 34816);
    __nv_bfloat16* Wext = (__nv_bfloat16*)(smraw + 69632);
    float* qh_sm  = (float*)(smraw + 73728);
    float* e_part = (float*)(smraw + 74240);    // [2][128]; init: bs + li
    float* alpha  = (float*)(smraw + 75264);    // [2][52] padded
    __nv_bfloat16* ab_sm = (__nv_bfloat16*)(smraw + 75776); // [<=40][128] 0.5a

    int tid = threadIdx.x, warp = tid >> 5, lane = tid & 31;
    int qq = lane >> 3, r7 = lane & 7;
    int grid = gridDim.x, bid = blockIdx.x;
    float qb = qbp[0];

    int nt = (NTILE2 - bid + grid - 1) / grid;  // tiles this CTA owns
    int rows2 = 2 * nt;                         // sessions (<= 34)
    int* lip = (int*)(e_part + 128);

    // ---------- init: W1, bs, li, gather, zero ----------
    if (tid < 128) {
        e_part[tid] = b1[tid] + b2[tid];        // bs
        qh_sm[tid] = 0.5f * q[tid];
    }
    if (tid < rows2) {
        int sess = 2 * (bid + (tid >> 1) * grid) + (tid & 1);
        lip[tid] = last_ixs[sess];
    }
    #pragma unroll
    for (int j = 0; j < 16; j++) {              // W1 -> bf16 smem
        int f4 = tid + j * 256, row = f4 >> 5, c4 = f4 & 31;
        st4bf(Wsm + row * SA + c4 * 4, ((const float4*)W1)[f4]);
    }
    #pragma unroll
    for (int j = 0; j < 34; j++)                // zero Asm (pad rows stay 0)
        ((uint32_t*)Asm)[tid + j * 256] = 0u;
    #pragma unroll
    for (int j = 0; j < 4; j++)                 // zero Wext (k>=2 stay 0)
        ((uint32_t*)Wext)[tid + j * 256] = 0u;
    __syncthreads();

    #pragma unroll
    for (int j = 0; j < 8; j++) {               // gather last rows -> Asm
        int f4 = tid + j * 256, row = f4 >> 5, c4 = f4 & 31;
        if (row < rows2)
            st4bf(Asm + row * SA + c4 * 4,
                  ((const float4*)(x + (size_t)lip[row] * 128))[c4]);
    }
    __syncthreads();

    uint32_t asm_u  = (uint32_t)__cvta_generic_to_shared(Asm);
    uint32_t wsm_u  = (uint32_t)__cvta_generic_to_shared(Wsm);
    uint32_t wext_u = (uint32_t)__cvta_generic_to_shared(Wext);

    // ---------- init MMA: a = x_last @ W1^T + bs ; ab_sm = bf16(0.5a) ------
    {
        int m0i = (warp & 1) * 32, n0i = (warp >> 1) * 32;
        uint32_t ab = asm_u + 2 * ((m0i + (qq & 1) * 8 + r7) * SA + (qq >> 1) * 8);
        uint32_t bb = wsm_u + 2 * ((n0i + (qq >> 1) * 8 + r7) * SA + (qq & 1) * 8);
        float c[2][4][4] = {};
        #pragma unroll
        for (int ks = 0; ks < 8; ks++) {
            uint32_t A0[4], A1[4], B0[4], B1[4];
            LDSM4(A0, ab + ks * 32);
            LDSM4(A1, ab + 16 * SA * 2 + ks * 32);
            LDSM4(B0, bb + ks * 32);
            LDSM4(B1, bb + 16 * SA * 2 + ks * 32);
            MMA16816(c[0][0], A0, B0[0], B0[1]);
            MMA16816(c[0][1], A0, B0[2], B0[3]);
            MMA16816(c[0][2], A0, B1[0], B1[1]);
            MMA16816(c[0][3], A0, B1[2], B1[3]);
            MMA16816(c[1][0], A1, B0[0], B0[1]);
            MMA16816(c[1][1], A1, B0[2], B0[3]);
            MMA16816(c[1][2], A1, B1[0], B1[1]);
            MMA16816(c[1][3], A1, B1[2], B1[3]);
        }
        #pragma unroll
        for (int mi = 0; mi < 2; mi++)
            #pragma unroll
            for (int ni = 0; ni < 4; ni++) {
                int col = n0i + ni * 8 + (lane & 3) * 2;
                #pragma unroll
                for (int r2 = 0; r2 < 2; r2++) {
                    int row = m0i + mi * 16 + (lane >> 2) + 8 * r2;
                    if (row < rows2) {
                        float a0 = 0.5f * (c[mi][ni][2 * r2]     + e_part[col]);
                        float a1 = 0.5f * (c[mi][ni][2 * r2 + 1] + e_part[col + 1]);
                        *(__nv_bfloat162*)(ab_sm + row * 128 + col) =
                            __floats2bfloat162_rn(a0, a1);
                    }
                }
            }
    }
    __syncthreads();                            // Wsm/Asm free; ab_sm done

    #pragma unroll
    for (int j = 0; j < 16; j++) {              // W2 -> bf16 smem (overwrite)
        int f4 = tid + j * 256, row = f4 >> 5, c4 = f4 & 31;
        st4bf(Wsm + row * SA + c4 * 4, ((const float4*)W2)[f4]);
    }

    // ---------- main loop setup ----------
    int m0 = (warp & 3) * 32;                   // warp tile: 32 rows x 64 cols
    int n0 = (warp >> 2) * 64;
    uint32_t abase = asm_u + 2 * ((m0 + (qq & 1) * 8 + r7) * SA + (qq >> 1) * 8);
    uint32_t bbase = wsm_u + 2 * ((n0 + (qq >> 1) * 8 + r7) * SA + (qq & 1) * 8);
    uint32_t ebase = wext_u + (n0 + (qq >> 1) * 8 + r7) * 32 + (qq & 1) * 16;

    // one-hot session-indicator A fragments (k=0 -> sess0, k=1 -> sess1)
    int klo = (lane & 3) * 2;
    uint32_t Aext[2][4];
    #pragma unroll
    for (int mi = 0; mi < 2; mi++) {
        #pragma unroll
        for (int h = 0; h < 2; h++) {
            int row = m0 + mi * 16 + (lane >> 2) + 8 * h;
            int sess = (row < 50) ? 0 : (row < 100) ? 1 : -1;
            uint32_t v = 0;
            if (sess == klo)     v |= 0x3F80u;
            if (sess == klo + 1) v |= 0x3F800000u;
            Aext[mi][h] = v;
        }
        Aext[mi][2] = 0u; Aext[mi][3] = 0u;
    }

    float csum = 0.f;                           // sum of 0.5*q over warp's cols
    #pragma unroll
    for (int g = 0; g < 16; g++) {
        float4 qv = *(const float4*)(qh_sm + n0 + g * 4);
        csum += qv.x + qv.y + qv.z + qv.w;
    }

    // ---------- prologue: fill Asm/Wext for first tile (all threads) -------
    {
        const float* xt = x + (size_t)bid * 12800;
        float4 v[13];
        #pragma unroll
        for (int j = 0; j < 13; j++) {
            int f4 = tid + j * 256;
            if (f4 < 3200) v[j] = ((const float4*)xt)[f4];
        }
        #pragma unroll
        for (int j = 0; j < 13; j++) {
            int f4 = tid + j * 256;
            if (f4 < 3200) {
                float4 w = v[j];
                w.x *= 0.5f; w.y *= 0.5f; w.z *= 0.5f; w.w *= 0.5f;
                st4bf(Asm + (f4 >> 5) * SA + (f4 & 31) * 4, w);
            }
        }
        Wext[(tid & 127) * 16 + (tid >> 7)] = ab_sm[(tid >> 7) * 128 + (tid & 127)];
    }
    __syncthreads();                            // first tile operands ready

    int it = 0;
    for (int t = bid; t < NTILE2; t += grid, it++) {
        const float* xt = x + (size_t)t * 12800;

        // ---- MMA: C = (0.5x)@W2^T + onehot@(0.5a)^T  (32x64 single pass) ----
        float c[2][8][4] = {};
        #pragma unroll
        for (int ks = 0; ks < 8; ks++) {
            uint32_t A0[4], A1[4], B0[4], B1[4], B2[4], B3[4];
            LDSM4(A0, abase + ks * 32);
            LDSM4(A1, abase + 16 * SA * 2 + ks * 32);
            LDSM4(B0, bbase + ks * 32);
            LDSM4(B1, bbase + 16 * SA * 2 + ks * 32);
            LDSM4(B2, bbase + 32 * SA * 2 + ks * 32);
            LDSM4(B3, bbase + 48 * SA * 2 + ks * 32);
            MMA16816(c[0][0], A0, B0[0], B0[1]); MMA16816(c[1][0], A1, B0[0], B0[1]);
            MMA16816(c[0][1], A0, B0[2], B0[3]); MMA16816(c[1][1], A1, B0[2], B0[3]);
            MMA16816(c[0][2], A0, B1[0], B1[1]); MMA16816(c[1][2], A1, B1[0], B1[1]);
            MMA16816(c[0][3], A0, B1[2], B1[3]); MMA16816(c[1][3], A1, B1[2], B1[3]);
            MMA16816(c[0][4], A0, B2[0], B2[1]); MMA16816(c[1][4], A1, B2[0], B2[1]);
            MMA16816(c[0][5], A0, B2[2], B2[3]); MMA16816(c[1][5], A1, B2[2], B2[3]);
            MMA16816(c[0][6], A0, B3[0], B3[1]); MMA16816(c[1][6], A1, B3[0], B3[1]);
            MMA16816(c[0][7], A0, B3[2], B3[3]); MMA16816(c[1][7], A1, B3[2], B3[3]);
        }
        {   // 9th k-step: per-session bias
            uint32_t B0[4], B1[4], B2[4], B3[4];
            LDSM4(B0, ebase);
            LDSM4(B1, ebase + 16 * 32);
            LDSM4(B2, ebase + 32 * 32);
            LDSM4(B3, ebase + 48 * 32);
            MMA16816(c[0][0], Aext[0], B0[0], B0[1]); MMA16816(c[1][0], Aext[1], B0[0], B0[1]);
            MMA16816(c[0][1], Aext[0], B0[2], B0[3]); MMA16816(c[1][1], Aext[1], B0[2], B0[3]);
            MMA16816(c[0][2], Aext[0], B1[0], B1[1]); MMA16816(c[1][2], Aext[1], B1[0], B1[1]);
            MMA16816(c[0][3], Aext[0], B1[2], B1[3]); MMA16816(c[1][3], Aext[1], B1[2], B1[3]);
            MMA16816(c[0][4], Aext[0], B2[0], B2[1]); MMA16816(c[1][4], Aext[1], B2[0], B2[1]);
            MMA16816(c[0][5], Aext[0], B2[2], B2[3]); MMA16816(c[1][5], Aext[1], B2[2], B2[3]);
            MMA16816(c[0][6], Aext[0], B3[0], B3[1]); MMA16816(c[1][6], Aext[1], B3[0], B3[1]);
            MMA16816(c[0][7], Aext[0], B3[2], B3[3]); MMA16816(c[1][7], Aext[1], B3[2], B3[3]);
        }

        // ---- epilogue: e partials = csum + sum 0.5*q*tanh(C) (no guards:
        //      rows>=100 have C=0, land in unread e_part slots) ----
        float pe[2][2] = {};
        #pragma unroll
        for (int ni = 0; ni < 8; ni++) {
            int col = n0 + ni * 8 + (lane & 3) * 2;
            float q0 = qh_sm[col], q1 = qh_sm[col + 1];
            #pragma unroll
            for (int mi = 0; mi < 2; mi++)
                #pragma unroll
                for (int r2 = 0; r2 < 2; r2++) {
                    float t0, t1;
                    asm("tanh.approx.f32 %0, %1;" : "=f"(t0) : "f"(c[mi][ni][2 * r2]));
                    asm("tanh.approx.f32 %0, %1;" : "=f"(t1) : "f"(c[mi][ni][2 * r2 + 1]));
                    pe[mi][r2] = fmaf(q0, t0, fmaf(q1, t1, pe[mi][r2]));
                }
        }
        #pragma unroll
        for (int mi = 0; mi < 2; mi++)
            #pragma unroll
            for (int r2 = 0; r2 < 2; r2++) {
                float vv = pe[mi][r2];
                vv += __shfl_xor_sync(0xffffffffu, vv, 1);
                vv += __shfl_xor_sync(0xffffffffu, vv, 2);
                if ((lane & 3) == 0) {
                    int row = m0 + mi * 16 + (lane >> 2) + 8 * r2;
                    e_part[(warp >> 2) * 128 + row] = vv + csum;
                }
            }
        __syncthreads();                        // sync1: e_part ready, MMA done

        // ---- warps0-1: softmax(t) || warps2-7: fill Asm/Wext(t+1) ----
        int tn = t + grid;
        if (warp < 2) {
            int er = warp * 50, ai = warp * 52;
            int i1 = er + lane;
            bool v2 = lane < 18;
            float e1 = e_part[i1] + e_part[128 + i1] + qb;
            float e2 = v2 ? (e_part[er + 32 + lane] + e_part[128 + er + 32 + lane] + qb)
                          : -1e30f;
            float m = fmaxf(e1, e2);
            #pragma unroll
            for (int o = 16; o; o >>= 1) m = fmaxf(m, __shfl_xor_sync(0xffffffffu, m, o));
            float z1 = __expf(e1 - m);
            float z2 = v2 ? __expf(e2 - m) : 0.f;
            float s = z1 + z2;
            #pragma unroll
            for (int o = 16; o; o >>= 1) s += __shfl_xor_sync(0xffffffffu, s, o);
            float inv = __frcp_rn(s);
            alpha[ai + lane] = z1 * inv;
            if (v2) alpha[ai + 32 + lane] = z2 * inv;
        } else if (tn < NTILE2) {
            const float* xt2 = x + (size_t)tn * 12800;
            int tf = tid - 64;                  // 0..191
            float4 v[17];
            #pragma unroll
            for (int j = 0; j < 17; j++) {
                int f4 = tf + j * 192;
                if (f4 < 3200) v[j] = ((const float4*)xt2)[f4];
            }
            #pragma unroll
            for (int j = 0; j < 17; j++) {
                int f4 = tf + j * 192;
                if (f4 < 3200) {
                    float4 w = v[j];
                    w.x *= 0.5f; w.y *= 0.5f; w.z *= 0.5f; w.w *= 0.5f;
                    st4bf(Asm + (f4 >> 5) * SA + (f4 & 31) * 4, w);
                }
            }
            #pragma unroll
            for (int i = tf; i < 256; i += 192)
                Wext[(i & 127) * 16 + (i >> 7)] =
                    ab_sm[(2 * (it + 1) + (i >> 7)) * 128 + (i & 127)];
        }
        __syncthreads();                        // sync2: alpha + next operands

        // ---- pooling(t): out[2t+s][col] = sum_j alpha_j * x_j[col] ----
        {
            int s = tid >> 7, col = tid & 127;
            const float* xr = xt + s * 6400 + col;
            const float* alp = alpha + s * 52;
            const float4* al4 = (const float4*)alp;
            float acc = 0.f;
            #pragma unroll
            for (int j4 = 0; j4 < 12; j4++) {
                float4 a4 = al4[j4];
                acc = fmaf(a4.x, xr[(j4 * 4 + 0) * 128], acc);
                acc = fmaf(a4.y, xr[(j4 * 4 + 1) * 128], acc);
                acc = fmaf(a4.z, xr[(j4 * 4 + 2) * 128], acc);
                acc = fmaf(a4.w, xr[(j4 * 4 + 3) * 128], acc);
            }
            acc = fmaf(alp[48], xr[48 * 128], acc);
            acc = fmaf(alp[49], xr[49 * 128], acc);
            out[(size_t)(2 * t + s) * 128 + col] = acc;
        }
        // no trailing sync: alpha(t) rewritten only after sync1 of tile t+1
    }
}

extern "C" void kernel_launch(void* const* d_in, const int* in_sizes, int n_in,
                              void* d_out, int out_size)
{
    const float* x   = (const float*)d_in[0];
    const float* W1w = (const float*)d_in[1];
    const float* W1b = (const float*)d_in[2];
    const float* W2w = (const float*)d_in[3];
    const float* W2b = (const float*)d_in[4];
    const float* qw  = (const float*)d_in[5];
    const float* qb  = (const float*)d_in[6];
    const int* last  = (const int*)d_in[8];
    float* out = (float*)d_out;

    cudaFuncSetAttribute(k2_main, cudaFuncAttributeMaxDynamicSharedMemorySize,
                         K2_SMEM);

    int nsm = 148;
    cudaDeviceGetAttribute(&nsm, cudaDevAttrMultiProcessorCount, 0);

    k2_main<<<2 * nsm, 256, K2_SMEM>>>(x, W1w, W1b, W2w, W2b, qw, qb, last, out);
}